// round 10
// baseline (speedup 1.0000x reference)
#include <cuda_runtime.h>
#include <cuda_bf16.h>

// Problem constants
#define BB 16
#define NN 64
#define HH 256
#define WW 256
#define HWXY (HH * WW)                 // 65536
#define TOTAL_ELEMS (BB * NN * HWXY)   // 67,108,864 per real/imag tensor
#define TOTAL_PIX (BB * HWXY)          // 1,048,576 pixels

__host__ __device__ constexpr int bitrev5(int m) {
    int r = 0;
    for (int i = 0; i < 5; i++) { r = (r << 1) | (m & 1); m >>= 1; }
    return r;
}

// Thread-PAIR cooperative 64-pt FFT: each thread of a pair holds 32 points
// (halves register pressure vs. 1-thread/pixel -> ~2x occupancy).
//   s = t&1. Thread s loads z[s*32 + j], j=0..31.
//   Stage 1 (span 32) exchanges via shfl.bfly(1):
//     s=0 keeps  u+v          -> feeds 32-pt FFT producing X[2k]
//     s=1 keeps (u-v)*W64^j   -> feeds 32-pt FFT producing X[2k+1]
//   Stages 2..6: fully-local unrolled 32-pt DIF FFT (bit-reversed out).
//   Final output index: n = 2*bitrev5(m) + s.
// OUT_MODE 0: d_out = interleaved complex (float2), 2*TOTAL_ELEMS floats.
// OUT_MODE 1: d_out = real part only, TOTAL_ELEMS floats.
template <int OUT_MODE>
__global__ void __launch_bounds__(128, 5)
fft64_pair_kernel(const float* __restrict__ re,
                  const float* __restrict__ im,
                  float* __restrict__ out)
{
    // W_64^k = (cos(pi k/32), -sin(pi k/32)), k = 0..31. Compile-time only.
    constexpr float TWR[32] = {
         1.000000000f,  0.995184727f,  0.980785280f,  0.956940336f,
         0.923879533f,  0.881921264f,  0.831469612f,  0.773010453f,
         0.707106781f,  0.634393284f,  0.555570233f,  0.471396737f,
         0.382683432f,  0.290284677f,  0.195090322f,  0.098017140f,
         0.000000000f, -0.098017140f, -0.195090322f, -0.290284677f,
        -0.382683432f, -0.471396737f, -0.555570233f, -0.634393284f,
        -0.707106781f, -0.773010453f, -0.831469612f, -0.881921264f,
        -0.923879533f, -0.956940336f, -0.980785280f, -0.995184727f
    };
    constexpr float TWI[32] = {   // = -sin(pi k/32)
        -0.000000000f, -0.098017140f, -0.195090322f, -0.290284677f,
        -0.382683432f, -0.471396737f, -0.555570233f, -0.634393284f,
        -0.707106781f, -0.773010453f, -0.831469612f, -0.881921264f,
        -0.923879533f, -0.956940336f, -0.980785280f, -0.995184727f,
        -1.000000000f, -0.995184727f, -0.980785280f, -0.956940336f,
        -0.923879533f, -0.881921264f, -0.831469612f, -0.773010453f,
        -0.707106781f, -0.634393284f, -0.555570233f, -0.471396737f,
        -0.382683432f, -0.290284677f, -0.195090322f, -0.098017140f
    };

    const unsigned t = blockIdx.x * 128u + threadIdx.x;
    const unsigned p = t >> 1;            // pixel id
    const unsigned s = t & 1u;            // half id within pair
    if (p >= (unsigned)TOTAL_PIX) return;
    const unsigned b  = p >> 16;          // / HWXY
    const unsigned hw = p & 0xFFFFu;      // % HWXY

    const size_t base = (size_t)b * NN * HWXY + hw;
    const size_t hoff = (size_t)(s * 32) * HWXY;
    const float* rp = re + base + hoff;
    const float* ip = im + base + hoff;

    float xr[32], xi[32];
#pragma unroll
    for (int j = 0; j < 32; j++) {
        xr[j] = rp[(size_t)j * HWXY];
        xi[j] = ip[(size_t)j * HWXY];
    }

    // ---- Stage 1 (span 32) across the thread pair via shfl.bfly(1) ----
#pragma unroll
    for (int j = 0; j < 32; j++) {
        const float or_ = __shfl_xor_sync(0xFFFFFFFFu, xr[j], 1);
        const float oi_ = __shfl_xor_sync(0xFFFFFFFFu, xi[j], 1);
        // s=0: u = mine, v = other  ->  u+v
        // s=1: u = other, v = mine  -> (u-v)*W64^j
        const float sr = xr[j] + or_;
        const float si = xi[j] + oi_;
        const float dr = or_ - xr[j];
        const float di = oi_ - xi[j];
        const float tr = dr * TWR[j] - di * TWI[j];
        const float ti = dr * TWI[j] + di * TWR[j];
        xr[j] = s ? tr : sr;
        xi[j] = s ? ti : si;
    }

    // ---- Stages 2..6: local 32-pt DIF FFT (W_32^k = W_64^{2k}) ----
#pragma unroll
    for (int st = 0; st < 5; st++) {
        const int half  = 16 >> st;
        const int tstep = 1 << st;
#pragma unroll
        for (int b0 = 0; b0 < 32; b0 += 2 * half) {
#pragma unroll
            for (int j = 0; j < half; j++) {
                const float ur = xr[b0 + j],        ui = xi[b0 + j];
                const float vr = xr[b0 + j + half], vi = xi[b0 + j + half];
                const float dr = ur - vr;
                const float di = ui - vi;
                xr[b0 + j] = ur + vr;
                xi[b0 + j] = ui + vi;
                const float wr = TWR[2 * j * tstep];   // W_32^{j*tstep}
                const float wi = TWI[2 * j * tstep];
                xr[b0 + j + half] = dr * wr - di * wi;
                xi[b0 + j + half] = dr * wi + di * wr;
            }
        }
    }

    // ---- Store: n = 2*bitrev5(m) + s ----
    if (OUT_MODE == 0) {
        float2* op = (float2*)out + base;
#pragma unroll
        for (int m = 0; m < 32; m++) {
            const int n2 = 2 * bitrev5(m);            // compile-time
            op[(size_t)(n2 + s) * HWXY] = make_float2(xr[m], xi[m]);
        }
    } else {
        float* op = out + base;
#pragma unroll
        for (int m = 0; m < 32; m++) {
            const int n2 = 2 * bitrev5(m);
            op[(size_t)(n2 + s) * HWXY] = xr[m];
        }
    }
}

extern "C" void kernel_launch(void* const* d_in, const int* in_sizes, int n_in,
                              void* d_out, int out_size)
{
    // Bind inputs BY SIZE: adc tensors have exactly B*N*H*W = 67,108,864
    // elements; the 128x128 DFT weight (16,384) is unused (compile-time twiddles).
    const float* re = nullptr;
    const float* im = nullptr;
    for (int i = 0; i < n_in; i++) {
        if (in_sizes[i] == TOTAL_ELEMS) {
            if (!re)      re = (const float*)d_in[i];
            else if (!im) im = (const float*)d_in[i];
        }
    }
    if (!im) {
        for (int i = 0; i < n_in; i++) {
            if (in_sizes[i] == 2 * TOTAL_ELEMS) {  // packed real+imag fallback
                re = (const float*)d_in[i];
                im = re + TOTAL_ELEMS;
            }
        }
    }
    if (!re || !im) return;

    const int block = 128;
    const int grid  = (2 * TOTAL_PIX) / block;   // 2 threads per pixel -> 16384

    if (out_size >= 2 * TOTAL_ELEMS) {
        fft64_pair_kernel<0><<<grid, block>>>(re, im, (float*)d_out);
    } else {
        fft64_pair_kernel<1><<<grid, block>>>(re, im, (float*)d_out);
    }
}

// round 11
// speedup vs baseline: 1.0003x; 1.0003x over previous
#include <cuda_runtime.h>
#include <cuda_bf16.h>

// Problem constants
#define BB 16
#define NN 64
#define HH 256
#define WW 256
#define HWXY (HH * WW)                 // 65536
#define TOTAL_ELEMS (BB * NN * HWXY)   // 67,108,864 per real/imag tensor
#define TOTAL_PIX (BB * HWXY)          // 1,048,576 pixels

__host__ __device__ constexpr int bitrev6(int m) {
    int r = 0;
    for (int i = 0; i < 6; i++) { r = (r << 1) | (m & 1); m >>= 1; }
    return r;
}

// One thread computes the full 64-point complex DFT of one (b,h,w) pixel.
// Streaming loads/stores (__ldcs/__stcs): zero-reuse workload, mark lines
// evict-first to minimize LTS churn (we sit at the ~6300 B/cyc LTS cap).
// OUT_MODE 0: d_out = interleaved complex (float2), 2*TOTAL_ELEMS floats.
// OUT_MODE 1: d_out = real part only, TOTAL_ELEMS floats.
template <int OUT_MODE>
__global__ void __launch_bounds__(128)
fft64_kernel(const float* __restrict__ re,
             const float* __restrict__ im,
             float* __restrict__ out)
{
    // W_64^k = (cos(pi k/32), -sin(pi k/32)). Compile-time -> FFMA immediates.
    constexpr float TWR[32] = {
         1.000000000f,  0.995184727f,  0.980785280f,  0.956940336f,
         0.923879533f,  0.881921264f,  0.831469612f,  0.773010453f,
         0.707106781f,  0.634393284f,  0.555570233f,  0.471396737f,
         0.382683432f,  0.290284677f,  0.195090322f,  0.098017140f,
         0.000000000f, -0.098017140f, -0.195090322f, -0.290284677f,
        -0.382683432f, -0.471396737f, -0.555570233f, -0.634393284f,
        -0.707106781f, -0.773010453f, -0.831469612f, -0.881921264f,
        -0.923879533f, -0.956940336f, -0.980785280f, -0.995184727f
    };
    constexpr float TWI[32] = {   // = -sin(pi k / 32)
        -0.000000000f, -0.098017140f, -0.195090322f, -0.290284677f,
        -0.382683432f, -0.471396737f, -0.555570233f, -0.634393284f,
        -0.707106781f, -0.773010453f, -0.831469612f, -0.881921264f,
        -0.923879533f, -0.956940336f, -0.980785280f, -0.995184727f,
        -1.000000000f, -0.995184727f, -0.980785280f, -0.956940336f,
        -0.923879533f, -0.881921264f, -0.831469612f, -0.773010453f,
        -0.707106781f, -0.634393284f, -0.555570233f, -0.471396737f,
        -0.382683432f, -0.290284677f, -0.195090322f, -0.098017140f
    };

    const unsigned p  = blockIdx.x * 128u + threadIdx.x;  // pixel id
    if (p >= (unsigned)TOTAL_PIX) return;
    const unsigned b  = p >> 16;          // / HWXY
    const unsigned hw = p & 0xFFFFu;      // % HWXY

    const size_t base = (size_t)b * NN * HWXY + hw;
    const float* rp = re + base;
    const float* ip = im + base;

    float2 x[64];
#pragma unroll
    for (int n = 0; n < 64; n++) {
        x[n].x = __ldcs(rp + (size_t)n * HWXY);
        x[n].y = __ldcs(ip + (size_t)n * HWXY);
    }

    // Fully-unrolled radix-2 DIF FFT, 6 stages. Outputs in bit-reversed order.
#pragma unroll
    for (int s = 0; s < 6; s++) {
        const int half  = 32 >> s;
        const int tstep = 1 << s;
#pragma unroll
        for (int b0 = 0; b0 < 64; b0 += 2 * half) {
#pragma unroll
            for (int j = 0; j < half; j++) {
                const float2 u = x[b0 + j];
                const float2 v = x[b0 + j + half];
                const float dx = u.x - v.x;
                const float dy = u.y - v.y;
                x[b0 + j].x = u.x + v.x;
                x[b0 + j].y = u.y + v.y;
                const float wr = TWR[j * tstep];
                const float wi = TWI[j * tstep];
                x[b0 + j + half].x = dx * wr - dy * wi;
                x[b0 + j + half].y = dx * wi + dy * wr;
            }
        }
    }

    if (OUT_MODE == 0) {
        float2* op = (float2*)out + base;
#pragma unroll
        for (int m = 0; m < 64; m++) {
            const int n = bitrev6(m);     // compile-time constant
            __stcs(&op[(size_t)n * HWXY], x[m]);
        }
    } else {
        float* op = out + base;
#pragma unroll
        for (int m = 0; m < 64; m++) {
            const int n = bitrev6(m);
            __stcs(&op[(size_t)n * HWXY], x[m].x);
        }
    }
}

extern "C" void kernel_launch(void* const* d_in, const int* in_sizes, int n_in,
                              void* d_out, int out_size)
{
    // Bind inputs BY SIZE: adc tensors have exactly B*N*H*W = 67,108,864
    // elements; the 128x128 DFT weight (16,384) is unused (compile-time twiddles).
    const float* re = nullptr;
    const float* im = nullptr;
    for (int i = 0; i < n_in; i++) {
        if (in_sizes[i] == TOTAL_ELEMS) {
            if (!re)      re = (const float*)d_in[i];
            else if (!im) im = (const float*)d_in[i];
        }
    }
    if (!im) {
        for (int i = 0; i < n_in; i++) {
            if (in_sizes[i] == 2 * TOTAL_ELEMS) {  // packed real+imag fallback
                re = (const float*)d_in[i];
                im = re + TOTAL_ELEMS;
            }
        }
    }
    if (!re || !im) return;

    const int block = 128;
    const int grid  = TOTAL_PIX / block;  // 8192

    if (out_size >= 2 * TOTAL_ELEMS) {
        fft64_kernel<0><<<grid, block>>>(re, im, (float*)d_out);
    } else {
        fft64_kernel<1><<<grid, block>>>(re, im, (float*)d_out);
    }
}